// round 14
// baseline (speedup 1.0000x reference)
#include <cuda_runtime.h>

#define B 256
#define C 50000
#define D 512
#define ALPHA 0.5f

// ---- scan blocks ----
#define OH_SLICES 8
#define NB_OH (B * OH_SLICES)       // 2048 scan blocks, first in grid
#define OH_ROW4 (C / 4)             // 12500 float4 per row
#define OH_PER_SLICE 1563
#define SCAN_ITERS 7                // 7*256 >= 1563

// ---- copy blocks: 256 thr x 8 float4 = 16 rows of D=512 ----
#define COPY_PER_THREAD 8
#define NB_COPY ((C * D / 4) / (256 * COPY_PER_THREAD))  // 3125, exact
#define NB_TOTAL (NB_OH + NB_COPY)

__device__ int g_labels[B];

// Kernel 1: onehot scan (iota-dot; finder block computes result[b] inline)
// + centers->new_centers bulk copy with WRITE-THROUGH stores (keeps L2 clean
// so the next graph replay's read ramp doesn't collide with dirty drain).
__global__ void __launch_bounds__(256) fused_kernel(
    const float* __restrict__ x,
    const float* __restrict__ onehot,
    const float* __restrict__ centers,
    float* __restrict__ result,
    float4* __restrict__ new_centers4) {
    int blk = blockIdx.x;
    int tid = threadIdx.x;

    if (blk < NB_OH) {
        // ========== scan: sum v[i]*(i+1) over slice ========================
        int b = blk >> 3;
        int slice = blk & 7;
        const float4* row = reinterpret_cast<const float4*>(onehot) +
                            (size_t)b * OH_ROW4;
        int lo = slice * OH_PER_SLICE;
        int hi = lo + OH_PER_SLICE;
        if (hi > OH_ROW4) hi = OH_ROW4;

        float acc = 0.0f;
        #pragma unroll
        for (int k = 0; k < SCAN_ITERS; k++) {
            int i = lo + tid + k * 256;
            float4 v = (i < hi) ? row[i] : make_float4(0.f, 0.f, 0.f, 0.f);
            float fi = (float)(4 * i);
            acc += v.x * (fi + 1.0f);
            acc += v.y * (fi + 2.0f);
            acc += v.z * (fi + 3.0f);
            acc += v.w * (fi + 4.0f);
        }

        __shared__ float s_warp[8];
        __shared__ float s_sum;
        #pragma unroll
        for (int off = 16; off > 0; off >>= 1)
            acc += __shfl_down_sync(0xFFFFFFFFu, acc, off);
        if ((tid & 31) == 0) s_warp[tid >> 5] = acc;
        __syncthreads();
        if (tid == 0) {
            float t = 0.0f;
            #pragma unroll
            for (int w = 0; w < 8; w++) t += s_warp[w];
            s_sum = t;
        }
        __syncthreads();

        float s = s_sum;
        if (s > 0.5f) {
            int l = (int)(s + 0.5f) - 1;   // exact: s == label+1 (< 2^24)
            if (tid == 0) g_labels[b] = l;

            // result[b] = ||x[b] - centers[l]||^2
            const float* xb = x + (size_t)b * D;
            const float* cl = centers + (size_t)l * D;
            float r = 0.0f;
            #pragma unroll
            for (int k = 0; k < D / 256; k++) {
                int d = tid + k * 256;
                float df = xb[d] - cl[d];
                r += df * df;
            }
            #pragma unroll
            for (int off = 16; off > 0; off >>= 1)
                r += __shfl_down_sync(0xFFFFFFFFu, r, off);
            if ((tid & 31) == 0) s_warp[tid >> 5] = r;
            __syncthreads();
            if (tid == 0) {
                float t = 0.0f;
                #pragma unroll
                for (int w = 0; w < 8; w++) t += s_warp[w];
                result[b] = t;
            }
        }
    } else {
        // ========== bulk copy: write-through stores ========================
        int cb = blk - NB_OH;
        const float4* src = reinterpret_cast<const float4*>(centers);
        size_t base = (size_t)cb * (256 * COPY_PER_THREAD) + tid;
        #pragma unroll
        for (int k = 0; k < COPY_PER_THREAD; k++) {
            size_t idx = base + (size_t)k * 256;
            __stwt(new_centers4 + idx, src[idx]);
        }
    }
}

// Kernel 2: row fixup. Block b recomputes the update for its label's row.
// Duplicate-label blocks compute the IDENTICAL value (fixed summation order
// m=0..255) so their concurrent writes are byte-identical and benign.
__global__ void __launch_bounds__(256) fixup_kernel(
    const float* __restrict__ x,
    const float* __restrict__ centers,
    float* __restrict__ new_centers) {
    int b = blockIdx.x;
    int tid = threadIdx.x;

    __shared__ int s_lab[B];
    s_lab[tid] = g_labels[tid];
    __syncthreads();

    int l = s_lab[b];

    // deterministic match sum: iterate samples in fixed order
    int n = 0;
    float sx0 = 0.0f, sx1 = 0.0f;
    #pragma unroll 4
    for (int m = 0; m < B; m++) {
        if (s_lab[m] == l) {
            n++;
            const float* xm = x + (size_t)m * D;
            sx0 += xm[tid];
            sx1 += xm[tid + 256];
        }
    }

    float inv = 1.0f / ((float)n + 1.0f);
    float fn = (float)n;
    size_t rb = (size_t)l * D;
    float c0 = centers[rb + tid];
    float c1 = centers[rb + tid + 256];
    new_centers[rb + tid]       = c0 - ALPHA * (fn * c0 - sx0) * inv;
    new_centers[rb + tid + 256] = c1 - ALPHA * (fn * c1 - sx1) * inv;
}

extern "C" void kernel_launch(void* const* d_in, const int* in_sizes, int n_in,
                              void* d_out, int out_size) {
    const float* x       = (const float*)d_in[0];
    const float* onehot  = (const float*)d_in[1];
    const float* centers = (const float*)d_in[2];

    float* result      = (float*)d_out;        // [B, 1]
    float* new_centers = (float*)d_out + B;    // [C, D]

    fused_kernel<<<NB_TOTAL, 256>>>(x, onehot, centers, result,
                                    reinterpret_cast<float4*>(new_centers));
    fixup_kernel<<<B, 256>>>(x, centers, new_centers);
}

// round 15
// speedup vs baseline: 1.2171x; 1.2171x over previous
#include <cuda_runtime.h>

#define B 256
#define C 50000
#define D 512
#define ALPHA 0.5f

// ---- K1: scan ----
#define OH_SLICES 8
#define NB_OH (B * OH_SLICES)       // 2048 blocks
#define OH_ROW4 (C / 4)             // 12500 float4 per row
#define OH_PER_SLICE 1563
#define SCAN_ITERS 7                // 7*256 >= 1563

// ---- K2: copy blocks (16 rows each) + fixup blocks ----
#define COPY_PER_THREAD 8
#define ROWS_PER_BLOCK 16
#define NB_COPY ((C * D / 4) / (256 * COPY_PER_THREAD))  // 3125, exact
#define NB_K2 (NB_COPY + B)

__device__ int g_labels[B];

// K1: onehot scan. Finder block writes g_labels[b] and result[b] inline.
__global__ void __launch_bounds__(256) scan_kernel(
    const float* __restrict__ x,
    const float* __restrict__ onehot,
    const float* __restrict__ centers,
    float* __restrict__ result) {
    int blk = blockIdx.x;
    int tid = threadIdx.x;

    int b = blk >> 3;
    int slice = blk & 7;
    const float4* row = reinterpret_cast<const float4*>(onehot) +
                        (size_t)b * OH_ROW4;
    int lo = slice * OH_PER_SLICE;
    int hi = lo + OH_PER_SLICE;
    if (hi > OH_ROW4) hi = OH_ROW4;

    float acc = 0.0f;
    #pragma unroll
    for (int k = 0; k < SCAN_ITERS; k++) {
        int i = lo + tid + k * 256;
        float4 v = (i < hi) ? row[i] : make_float4(0.f, 0.f, 0.f, 0.f);
        float fi = (float)(4 * i);
        acc += v.x * (fi + 1.0f);
        acc += v.y * (fi + 2.0f);
        acc += v.z * (fi + 3.0f);
        acc += v.w * (fi + 4.0f);
    }

    __shared__ float s_warp[8];
    __shared__ float s_sum;
    #pragma unroll
    for (int off = 16; off > 0; off >>= 1)
        acc += __shfl_down_sync(0xFFFFFFFFu, acc, off);
    if ((tid & 31) == 0) s_warp[tid >> 5] = acc;
    __syncthreads();
    if (tid == 0) {
        float t = 0.0f;
        #pragma unroll
        for (int w = 0; w < 8; w++) t += s_warp[w];
        s_sum = t;
    }
    __syncthreads();

    float s = s_sum;
    if (s > 0.5f) {
        int l = (int)(s + 0.5f) - 1;   // exact: s == label+1 (< 2^24)
        if (tid == 0) g_labels[b] = l;

        // result[b] = ||x[b] - centers[l]||^2
        const float* xb = x + (size_t)b * D;
        const float* cl = centers + (size_t)l * D;
        float r = 0.0f;
        #pragma unroll
        for (int k = 0; k < D / 256; k++) {
            int d = tid + k * 256;
            float df = xb[d] - cl[d];
            r += df * df;
        }
        #pragma unroll
        for (int off = 16; off > 0; off >>= 1)
            r += __shfl_down_sync(0xFFFFFFFFu, r, off);
        if ((tid & 31) == 0) s_warp[tid >> 5] = r;
        __syncthreads();
        if (tid == 0) {
            float t = 0.0f;
            #pragma unroll
            for (int w = 0; w < 8; w++) t += s_warp[w];
            result[b] = t;
        }
    }
}

// K2: copy blocks skip touched rows (predicated stores); fixup blocks are
// the exclusive writers of touched rows. No WAW conflict anywhere.
__global__ void __launch_bounds__(256) copy_fixup_kernel(
    const float* __restrict__ x,
    const float* __restrict__ centers,
    float* __restrict__ new_centers) {
    int blk = blockIdx.x;
    int tid = threadIdx.x;

    if (blk < NB_COPY) {
        const float4* src = reinterpret_cast<const float4*>(centers);
        float4* dst = reinterpret_cast<float4*>(new_centers);
        size_t base = (size_t)blk * (256 * COPY_PER_THREAD) + tid;

        // batch 1: issue 4 src loads BEFORE touching labels (keep MLP)
        float4 v0 = src[base + 0 * 256];
        float4 v1 = src[base + 1 * 256];
        float4 v2 = src[base + 2 * 256];
        float4 v3 = src[base + 3 * 256];

        // labels + touched-row mask (overlaps with loads in flight)
        __shared__ int s_lab[B];
        __shared__ unsigned int s_mask;
        s_lab[tid] = g_labels[tid];
        if (tid == 0) s_mask = 0u;
        __syncthreads();
        int r0 = blk * ROWS_PER_BLOCK;
        int l = s_lab[tid];
        if ((unsigned)(l - r0) < (unsigned)ROWS_PER_BLOCK)
            atomicOr(&s_mask, 1u << (l - r0));
        __syncthreads();
        unsigned int mask = s_mask;
        int half = tid >> 7;   // row-within-pair: ri = 2k + half

        if (!((mask >> (0 + half)) & 1u)) dst[base + 0 * 256] = v0;
        if (!((mask >> (2 + half)) & 1u)) dst[base + 1 * 256] = v1;
        if (!((mask >> (4 + half)) & 1u)) dst[base + 2 * 256] = v2;
        if (!((mask >> (6 + half)) & 1u)) dst[base + 3 * 256] = v3;

        // batch 2
        float4 w0 = src[base + 4 * 256];
        float4 w1 = src[base + 5 * 256];
        float4 w2 = src[base + 6 * 256];
        float4 w3 = src[base + 7 * 256];
        if (!((mask >> (8  + half)) & 1u)) dst[base + 4 * 256] = w0;
        if (!((mask >> (10 + half)) & 1u)) dst[base + 5 * 256] = w1;
        if (!((mask >> (12 + half)) & 1u)) dst[base + 6 * 256] = w2;
        if (!((mask >> (14 + half)) & 1u)) dst[base + 7 * 256] = w3;
    } else {
        // ---- fixup: exclusive writer of touched rows ----
        int b = blk - NB_COPY;

        __shared__ int s_lab[B];
        __shared__ int s_match[B];
        __shared__ int s_cnt;
        __shared__ int s_first;

        s_lab[tid] = g_labels[tid];
        if (tid == 0) { s_cnt = 0; s_first = B; }
        __syncthreads();

        int l = s_lab[b];
        if (s_lab[tid] == l) {
            int pos = atomicAdd(&s_cnt, 1);
            s_match[pos] = tid;
            atomicMin(&s_first, tid);
        }
        __syncthreads();

        if (b != s_first) return;   // one writer per class row

        int n = s_cnt;
        float inv = 1.0f / ((float)n + 1.0f);
        float fn = (float)n;
        #pragma unroll
        for (int k = 0; k < D / 256; k++) {
            int d = tid + k * 256;
            float sx = 0.0f;
            for (int m = 0; m < n; m++)
                sx += x[(size_t)s_match[m] * D + d];
            float c = centers[(size_t)l * D + d];
            new_centers[(size_t)l * D + d] = c - ALPHA * (fn * c - sx) * inv;
        }
    }
}

extern "C" void kernel_launch(void* const* d_in, const int* in_sizes, int n_in,
                              void* d_out, int out_size) {
    const float* x       = (const float*)d_in[0];
    const float* onehot  = (const float*)d_in[1];
    const float* centers = (const float*)d_in[2];

    float* result      = (float*)d_out;        // [B, 1]
    float* new_centers = (float*)d_out + B;    // [C, D]

    scan_kernel<<<NB_OH, 256>>>(x, onehot, centers, result);
    copy_fixup_kernel<<<NB_K2, 256>>>(x, centers, new_centers);
}